// round 9
// baseline (speedup 1.0000x reference)
#include <cuda_runtime.h>
#include <math.h>

#define NQ 4
#define NL 3
#define NG (NL * NQ)

// ---------------------------------------------------------------------------
// Batch-invariant data written by prep kernel.
// For g < 8 (layers 0,1): g_rotp[g*8+k] = Rot entries dup-packed {v,v}:
//   r00.r, r00.i, r01.r, r01.i, r10.r, r10.i, r11.r, r11.i
// For g >= 8 (last layer, RZ(om) dropped — diagonal before measurement):
//   ct, st, -st, -ct, cos(phi), sin(phi), -sin(phi), 0   (dup-packed)
// g_scaleh[g] = scaling[l,q] * pi * 0.5  (half-angle factor)
// ---------------------------------------------------------------------------
__device__ __align__(16) float2 g_rotp[NG * 8];
__device__ __align__(16) float g_scaleh[NG];

// ---------------------------------------------------------------------------
// Packed f32x2 primitives (Blackwell FFMA2 path — PTX-only, ptxas won't emit)
// ---------------------------------------------------------------------------
typedef unsigned long long f2;

__device__ __forceinline__ f2 pack2(float lo, float hi) {
    f2 r; asm("mov.b64 %0, {%1, %2};" : "=l"(r) : "f"(lo), "f"(hi)); return r;
}
__device__ __forceinline__ void unpack2(f2 v, float& lo, float& hi) {
    asm("mov.b64 {%0, %1}, %2;" : "=f"(lo), "=f"(hi) : "l"(v));
}
__device__ __forceinline__ f2 fma2(f2 a, f2 b, f2 c) {
    f2 d; asm("fma.rn.f32x2 %0, %1, %2, %3;" : "=l"(d) : "l"(a), "l"(b), "l"(c)); return d;
}
__device__ __forceinline__ f2 mul2(f2 a, f2 b) {
    f2 d; asm("mul.rn.f32x2 %0, %1, %2;" : "=l"(d) : "l"(a), "l"(b)); return d;
}
__device__ __forceinline__ f2 add2(f2 a, f2 b) {
    f2 d; asm("add.rn.f32x2 %0, %1, %2;" : "=l"(d) : "l"(a), "l"(b)); return d;
}

struct Cp { f2 r, i; };  // packed complex: lane0 = sample A, lane1 = sample B

// (a*b) complex, packed; NEG1 = packed {-1,-1}
__device__ __forceinline__ Cp cmulp(Cp a, Cp b, f2 NEG1) {
    Cp o;
    f2 t = mul2(a.i, b.i);
    o.r = fma2(a.r, b.r, mul2(t, NEG1));
    o.i = fma2(a.i, b.r, mul2(a.r, b.i));
    return o;
}

__device__ __forceinline__ float fast_tanh(float v) {
    float e = __expf(2.0f * v);
    return 1.0f - __fdividef(2.0f, e + 1.0f);
}

// ---------------------------------------------------------------------------
// Prep kernel
// ---------------------------------------------------------------------------
__global__ void prep_kernel(const float* __restrict__ w, const float* __restrict__ sc) {
    int g = threadIdx.x;
    if (g < NG) {
        float phi = w[3 * g + 0];
        float th  = w[3 * g + 1];
        float om  = w[3 * g + 2];
        float e[8];
        if (g < 2 * NQ) {
            // Full Rot(phi, theta, omega) = RZ(om) RY(th) RZ(phi)
            float ct, st, cp, sp, cm, sm;
            sincosf(0.5f * th, &st, &ct);
            sincosf(0.5f * (phi + om), &sp, &cp);
            sincosf(0.5f * (phi - om), &sm, &cm);
            e[0] =  ct * cp;  e[1] = -ct * sp;   // r00
            e[2] = -st * cm;  e[3] = -st * sm;   // r01
            e[4] =  st * cm;  e[5] = -st * sm;   // r10
            e[6] =  ct * cp;  e[7] =  ct * sp;   // r11
        } else {
            // Last layer: RZ(om) dropped (diag before measurement, CNOTs keep
            // it diagonal, |amp|^2 invariant). Store RY(th) + e^{i phi}.
            float ct, st, er, ei;
            sincosf(0.5f * th, &st, &ct);
            sincosf(phi, &ei, &er);
            e[0] = ct; e[1] = st; e[2] = -st; e[3] = -ct;
            e[4] = er; e[5] = ei; e[6] = -ei; e[7] = 0.0f;
        }
#pragma unroll
        for (int k = 0; k < 8; k++) g_rotp[g * 8 + k] = make_float2(e[k], e[k]);
        g_scaleh[g] = sc[g] * (3.14159265358979323846f * 0.5f);
    }
}

// ---------------------------------------------------------------------------
// Fused gate up to GLOBAL PHASE (layers 0..NL-2), sincos precomputed:
//   U' = Rot @ diag(1, p) @ RY(ang),  p = e^{i ang/2} = (ch, sh)
// ---------------------------------------------------------------------------
__device__ __forceinline__ void build_u_p(int g, f2 sh, f2 ch, f2 NEG1,
                                          Cp& u00, Cp& u01, Cp& u10, Cp& u11) {
    f2 nsh = mul2(sh, NEG1);

    const ulonglong2* rp = reinterpret_cast<const ulonglong2*>(g_rotp) + g * 4;
    ulonglong2 e0 = rp[0], e1 = rp[1], e2 = rp[2], e3 = rp[3];
    Cp r00 = {e0.x, e0.y}, r01 = {e1.x, e1.y};
    Cp r10 = {e2.x, e2.y}, r11 = {e3.x, e3.y};

    // D col1 = Rot col1 * p
    Cp d01, d11;
    d01.r = fma2(r01.i, nsh, mul2(r01.r, ch));
    d01.i = fma2(r01.i, ch,  mul2(r01.r, sh));
    d11.r = fma2(r11.i, nsh, mul2(r11.r, ch));
    d11.i = fma2(r11.i, ch,  mul2(r11.r, sh));

    // U = [ (r00, d01) ; (r10, d11) ] @ [[ch, -sh], [sh, ch]]
    u00.r = fma2(sh, d01.r, mul2(ch, r00.r));
    u00.i = fma2(sh, d01.i, mul2(ch, r00.i));
    u01.r = fma2(nsh, r00.r, mul2(ch, d01.r));
    u01.i = fma2(nsh, r00.i, mul2(ch, d01.i));
    u10.r = fma2(sh, d11.r, mul2(ch, r10.r));
    u10.i = fma2(sh, d11.i, mul2(ch, r10.i));
    u11.r = fma2(nsh, r10.r, mul2(ch, d11.r));
    u11.i = fma2(nsh, r10.i, mul2(ch, d11.i));
}

// Last-layer gate (RZ(om) dropped): U = RY(th) @ diag(1, pp) @ RY(ang),
// pp = e^{i(phi + ang/2)}.
__device__ __forceinline__ void build_u_last(int g, f2 sh, f2 ch,
                                             Cp& u00, Cp& u01, Cp& u10, Cp& u11) {
    const ulonglong2* rp = reinterpret_cast<const ulonglong2*>(g_rotp) + g * 4;
    ulonglong2 e0 = rp[0], e1 = rp[1], e2 = rp[2], e3 = rp[3];
    f2 ct = e0.x, st = e0.y, nst = e1.x, nct = e1.y;
    f2 er = e2.x, ei = e2.y, nei = e3.x;

    f2 ppr = fma2(nei, sh, mul2(er, ch));   // cos(phi + a/2)
    f2 ppi = fma2(ei,  ch, mul2(er, sh));   // sin(phi + a/2)

    f2 A  = mul2(ct,  ch);   // ct·ch
    f2 Bp = mul2(nst, sh);   // -st·sh
    f2 C  = mul2(ct,  sh);   // ct·sh
    f2 nC = mul2(nct, sh);   // -ct·sh
    f2 D  = mul2(st,  ch);   // st·ch
    f2 nD = mul2(nst, ch);   // -st·ch

    u00.r = fma2(Bp, ppr, A);  u00.i = mul2(Bp, ppi);
    u01.r = fma2(nD, ppr, nC); u01.i = mul2(nD, ppi);
    u10.r = fma2(C,  ppr, D);  u10.i = mul2(C,  ppi);
    u11.r = fma2(A,  ppr, Bp); u11.i = mul2(A,  ppi);
}

// Column-0-only variant for layer 0 (state |0000>).
__device__ __forceinline__ void build_u_col0(int g, f2 sh, f2 ch, f2 NEG1,
                                             Cp& u00, Cp& u10) {
    f2 nsh = mul2(sh, NEG1);

    const ulonglong2* rp = reinterpret_cast<const ulonglong2*>(g_rotp) + g * 4;
    ulonglong2 e0 = rp[0], e1 = rp[1], e2 = rp[2], e3 = rp[3];
    Cp r00 = {e0.x, e0.y}, r01 = {e1.x, e1.y};
    Cp r10 = {e2.x, e2.y}, r11 = {e3.x, e3.y};

    Cp d01, d11;
    d01.r = fma2(r01.i, nsh, mul2(r01.r, ch));
    d01.i = fma2(r01.i, ch,  mul2(r01.r, sh));
    d11.r = fma2(r11.i, nsh, mul2(r11.r, ch));
    d11.i = fma2(r11.i, ch,  mul2(r11.r, sh));

    u00.r = fma2(sh, d01.r, mul2(ch, r00.r));
    u00.i = fma2(sh, d01.i, mul2(ch, r00.i));
    u10.r = fma2(sh, d11.r, mul2(ch, r10.r));
    u10.i = fma2(sh, d11.i, mul2(ch, r10.i));
}

// Amplitude index: i = b0*8 + b1*4 + b2*2 + b3 (qubit q -> mask 8>>q).
template <int M>
__device__ __forceinline__ void apply_gate_p(Cp* s, Cp u00, Cp u01, Cp u10, Cp u11,
                                             f2 NEG1) {
    f2 n00 = mul2(u00.i, NEG1), n01 = mul2(u01.i, NEG1);
    f2 n10 = mul2(u10.i, NEG1), n11 = mul2(u11.i, NEG1);
#pragma unroll
    for (int i = 0; i < 16; i++) {
        if ((i & M) == 0) {
            Cp a0 = s[i], a1 = s[i | M];
            f2 r0 = mul2(u00.r, a0.r); r0 = fma2(n00, a0.i, r0);
            r0 = fma2(u01.r, a1.r, r0); r0 = fma2(n01, a1.i, r0);
            f2 i0 = mul2(u00.r, a0.i); i0 = fma2(u00.i, a0.r, i0);
            i0 = fma2(u01.r, a1.i, i0); i0 = fma2(u01.i, a1.r, i0);
            f2 r1 = mul2(u10.r, a0.r); r1 = fma2(n10, a0.i, r1);
            r1 = fma2(u11.r, a1.r, r1); r1 = fma2(n11, a1.i, r1);
            f2 i1 = mul2(u10.r, a0.i); i1 = fma2(u10.i, a0.r, i1);
            i1 = fma2(u11.r, a1.i, i1); i1 = fma2(u11.i, a1.r, i1);
            s[i].r = r0; s[i].i = i0;
            s[i | M].r = r1; s[i | M].i = i1;
        }
    }
}

template <int MC, int MT>
__device__ __forceinline__ void cnotp(Cp* s) {
#pragma unroll
    for (int i = 0; i < 16; i++) {
        if ((i & MC) && !(i & MT)) {
            Cp tmp = s[i]; s[i] = s[i | MT]; s[i | MT] = tmp;
        }
    }
}

__device__ __forceinline__ void cnot_ring_p(Cp* s) {
    cnotp<8, 4>(s);
    cnotp<4, 2>(s);
    cnotp<2, 1>(s);
    cnotp<1, 8>(s);
}

// Batch-compute the packed (sh, ch) for one layer's 4 gates: all 8 MUFU
// sincos chains issued before any consumer — hides MUFU latency under the
// surrounding FFMA2 stream.
__device__ __forceinline__ void sincos_layer(const float* tqA, const float* tqB,
                                             const float4 sc, f2* shv, f2* chv) {
    float a0A = tqA[0] * sc.x, a0B = tqB[0] * sc.x;
    float a1A = tqA[1] * sc.y, a1B = tqB[1] * sc.y;
    float a2A = tqA[2] * sc.z, a2B = tqB[2] * sc.z;
    float a3A = tqA[3] * sc.w, a3B = tqB[3] * sc.w;
    float s0A, c0A, s0B, c0B, s1A, c1A, s1B, c1B;
    float s2A, c2A, s2B, c2B, s3A, c3A, s3B, c3B;
    __sincosf(a0A, &s0A, &c0A); __sincosf(a0B, &s0B, &c0B);
    __sincosf(a1A, &s1A, &c1A); __sincosf(a1B, &s1B, &c1B);
    __sincosf(a2A, &s2A, &c2A); __sincosf(a2B, &s2B, &c2B);
    __sincosf(a3A, &s3A, &c3A); __sincosf(a3B, &s3B, &c3B);
    shv[0] = pack2(s0A, s0B); chv[0] = pack2(c0A, c0B);
    shv[1] = pack2(s1A, s1B); chv[1] = pack2(c1A, c1B);
    shv[2] = pack2(s2A, s2B); chv[2] = pack2(c2A, c2B);
    shv[3] = pack2(s3A, s3B); chv[3] = pack2(c3A, c3B);
}

__global__ __launch_bounds__(128)
void qsim_kernel(const float* __restrict__ x, float* __restrict__ out, int B2) {
    int t = blockIdx.x * blockDim.x + threadIdx.x;
    if (t >= B2) return;

    const f2 M2   = pack2(-2.0f, -2.0f);
    const f2 NEG1 = pack2(-1.0f, -1.0f);

    // Hoist all 12 half-angle scale factors as 3 vector loads.
    const float4* scp = reinterpret_cast<const float4*>(g_scaleh);
    float4 sc0 = scp[0], sc1 = scp[1], sc2 = scp[2];

    const float4* x4 = reinterpret_cast<const float4*>(x);
    float4 xa = x4[2 * t], xb = x4[2 * t + 1];
    float tqA[NQ] = {fast_tanh(xa.x), fast_tanh(xa.y), fast_tanh(xa.z), fast_tanh(xa.w)};
    float tqB[NQ] = {fast_tanh(xb.x), fast_tanh(xb.y), fast_tanh(xb.z), fast_tanh(xb.w)};

    Cp s[16];

    // ---- Layer 0: |0000> -> product state from column 0 of each U, then ring
    {
        f2 shv[NQ], chv[NQ];
        sincos_layer(tqA, tqB, sc0, shv, chv);
        Cp c0[NQ], c1[NQ];
#pragma unroll
        for (int q = 0; q < NQ; q++)
            build_u_col0(q, shv[q], chv[q], NEG1, c0[q], c1[q]);

        Cp t01[4], t23[4];
        t01[0] = cmulp(c0[0], c0[1], NEG1); t01[1] = cmulp(c0[0], c1[1], NEG1);
        t01[2] = cmulp(c1[0], c0[1], NEG1); t01[3] = cmulp(c1[0], c1[1], NEG1);
        t23[0] = cmulp(c0[2], c0[3], NEG1); t23[1] = cmulp(c0[2], c1[3], NEG1);
        t23[2] = cmulp(c1[2], c0[3], NEG1); t23[3] = cmulp(c1[2], c1[3], NEG1);
#pragma unroll
        for (int i = 0; i < 16; i++) s[i] = cmulp(t01[i >> 2], t23[i & 3], NEG1);
        cnot_ring_p(s);
    }

    // ---- Layer 1: generic fused gates (sincos batched up front)
    {
        f2 shv[NQ], chv[NQ];
        sincos_layer(tqA, tqB, sc1, shv, chv);
#pragma unroll
        for (int q = 0; q < NQ; q++) {
            Cp u00, u01, u10, u11;
            build_u_p(NQ + q, shv[q], chv[q], NEG1, u00, u01, u10, u11);
            if (q == 0) apply_gate_p<8>(s, u00, u01, u10, u11, NEG1);
            if (q == 1) apply_gate_p<4>(s, u00, u01, u10, u11, NEG1);
            if (q == 2) apply_gate_p<2>(s, u00, u01, u10, u11, NEG1);
            if (q == 3) apply_gate_p<1>(s, u00, u01, u10, u11, NEG1);
        }
        cnot_ring_p(s);
    }

    // ---- Layer 2 (last): RZ(om) dropped, cheap build (sincos batched)
    {
        f2 shv[NQ], chv[NQ];
        sincos_layer(tqA, tqB, sc2, shv, chv);
#pragma unroll
        for (int q = 0; q < NQ; q++) {
            Cp u00, u01, u10, u11;
            build_u_last(2 * NQ + q, shv[q], chv[q], u00, u01, u10, u11);
            if (q == 0) apply_gate_p<8>(s, u00, u01, u10, u11, NEG1);
            if (q == 1) apply_gate_p<4>(s, u00, u01, u10, u11, NEG1);
            if (q == 2) apply_gate_p<2>(s, u00, u01, u10, u11, NEG1);
            if (q == 3) apply_gate_p<1>(s, u00, u01, u10, u11, NEG1);
        }
        cnot_ring_p(s);
    }

    // ---- Probabilities and <Z_w>, shared partial sums
    f2 p[16];
#pragma unroll
    for (int i = 0; i < 16; i++) p[i] = fma2(s[i].r, s[i].r, mul2(s[i].i, s[i].i));

    f2 a[8], bb[4], c[2];
#pragma unroll
    for (int k = 0; k < 8; k++) a[k] = add2(p[2 * k], p[2 * k + 1]);
#pragma unroll
    for (int k = 0; k < 4; k++) bb[k] = add2(a[2 * k], a[2 * k + 1]);
    c[0] = add2(bb[0], bb[1]); c[1] = add2(bb[2], bb[3]);
    f2 tot = add2(c[0], c[1]);

    // z_w = tot - 2 * (sum of p where bit_w set)
    f2 s0 = c[1];                                            // mask 8
    f2 s1 = add2(bb[1], bb[3]);                              // mask 4
    f2 s2 = add2(add2(a[1], a[3]), add2(a[5], a[7]));        // mask 2
    f2 s3 = add2(add2(add2(p[1], p[3]), add2(p[5], p[7])),
                 add2(add2(p[9], p[11]), add2(p[13], p[15])));   // mask 1
    f2 z0 = fma2(M2, s0, tot);
    f2 z1 = fma2(M2, s1, tot);
    f2 z2 = fma2(M2, s2, tot);
    f2 z3 = fma2(M2, s3, tot);

    float z0A, z0B, z1A, z1B, z2A, z2B, z3A, z3B;
    unpack2(z0, z0A, z0B); unpack2(z1, z1A, z1B);
    unpack2(z2, z2A, z2B); unpack2(z3, z3A, z3B);

    float4* o4 = reinterpret_cast<float4*>(out);
    o4[2 * t]     = make_float4(z0A, z1A, z2A, z3A);
    o4[2 * t + 1] = make_float4(z0B, z1B, z2B, z3B);
}

extern "C" void kernel_launch(void* const* d_in, const int* in_sizes, int n_in,
                              void* d_out, int out_size) {
    const float* x  = (const float*)d_in[0];   // [B, 4]
    const float* w  = (const float*)d_in[1];   // [3, 4, 3]
    const float* sc = (const float*)d_in[2];   // [3, 4]
    float* out = (float*)d_out;                // [B, 4]
    int B = in_sizes[0] / NQ;
    int B2 = B / 2;                            // 2 samples per thread

    prep_kernel<<<1, 32>>>(w, sc);
    int threads = 128;
    int blocks = (B2 + threads - 1) / threads;
    qsim_kernel<<<blocks, threads>>>(x, out, B2);
}